// round 3
// baseline (speedup 1.0000x reference)
#include <cuda_runtime.h>

// Scratch via __device__ globals (no allocations allowed).
__device__ float    g_part[8192];
__device__ unsigned g_count = 0;   // self-resetting ticket -> deterministic per call

// Fast sqrt: bit-hack rsqrt + 2 Newton iterations (FMA pipe only, no MUFU).
// Max rel err ~5e-6. Returns exactly 0 for x == 0.
__device__ __forceinline__ float fsqrt_fast(float x) {
    float xh = 0.5f * x;
    float r = __uint_as_float(0x5f3759dfu - (__float_as_uint(x) >> 1));
    r = r * (1.5f - xh * r * r);
    r = r * (1.5f - xh * r * r);
    return x * r;
}

// Shapes fixed: [8,3,16,256,256] fp32, H=W=256. Row = 64 float4.
// Each thread: 4 consecutive float4 (16 elems) of one row.
// TV magnitude: sqrt((x[h,w]-x[h,w+1])^2 + (x[h,w]-x[h+1,w])^2), circular.
__global__ void __launch_bounds__(256) tv_fused_kernel(const float4* __restrict__ in4,
                                                       float* __restrict__ out,
                                                       float inv_n) {
    const int t  = blockIdx.x * 256 + threadIdx.x;
    const int q0 = t << 2;            // first float4 index (same row)
    const int r  = q0 >> 6;           // global row id (plane*256 + h)
    const int w4 = q0 & 63;           // float4 offset within row
    const int h  = r & 255;
    const int plane = r >> 8;
    const int rowbase = r << 6;
    const int dbase   = ((plane << 8) | ((h + 1) & 255)) << 6;  // circular down row

    const float4 a0 = in4[rowbase + w4];
    const float4 a1 = in4[rowbase + w4 + 1];
    const float4 a2 = in4[rowbase + w4 + 2];
    const float4 a3 = in4[rowbase + w4 + 3];
    const float4 b  = in4[rowbase + ((w4 + 4) & 63)];           // circular right wrap
    const float4 c0 = in4[dbase + w4];
    const float4 c1 = in4[dbase + w4 + 1];
    const float4 c2 = in4[dbase + w4 + 2];
    const float4 c3 = in4[dbase + w4 + 3];

    float acc = 0.0f;
    #define TV_PROC(a, nx, c)                                              \
    {                                                                      \
        float dx0 = a.x - a.y,  dy0 = a.x - c.x;                           \
        float dx1 = a.y - a.z,  dy1 = a.y - c.y;                           \
        float dx2 = a.z - a.w,  dy2 = a.z - c.z;                           \
        float dx3 = a.w - (nx), dy3 = a.w - c.w;                           \
        acc += fsqrt_fast(fmaf(dx0, dx0, dy0 * dy0));                      \
        acc += fsqrt_fast(fmaf(dx1, dx1, dy1 * dy1));                      \
        acc += fsqrt_fast(fmaf(dx2, dx2, dy2 * dy2));                      \
        acc += fsqrt_fast(fmaf(dx3, dx3, dy3 * dy3));                      \
    }
    TV_PROC(a0, a1.x, c0)
    TV_PROC(a1, a2.x, c1)
    TV_PROC(a2, a3.x, c2)
    TV_PROC(a3, b.x,  c3)
    #undef TV_PROC

    // Warp reduce
    #pragma unroll
    for (int o = 16; o > 0; o >>= 1)
        acc += __shfl_xor_sync(0xFFFFFFFFu, acc, o);

    __shared__ float warpsum[8];
    __shared__ bool  s_last;
    const int lane = threadIdx.x & 31;
    const int wid  = threadIdx.x >> 5;
    if (lane == 0) warpsum[wid] = acc;
    if (threadIdx.x == 0) s_last = false;
    __syncthreads();

    if (threadIdx.x == 0) {
        float bsum = warpsum[0] + warpsum[1] + warpsum[2] + warpsum[3]
                   + warpsum[4] + warpsum[5] + warpsum[6] + warpsum[7];
        g_part[blockIdx.x] = bsum;
        __threadfence();
        unsigned ticket = atomicAdd(&g_count, 1u);
        if (ticket == gridDim.x - 1) s_last = true;
    }
    __syncthreads();

    // Last block to arrive reduces all partials and writes the output.
    if (s_last) {
        double d = 0.0;
        for (int i = threadIdx.x; i < (int)gridDim.x; i += 256)
            d += (double)g_part[i];
        #pragma unroll
        for (int o = 16; o > 0; o >>= 1)
            d += __shfl_xor_sync(0xFFFFFFFFu, d, o);
        __shared__ double dws[8];
        if (lane == 0) dws[wid] = d;
        __syncthreads();
        if (threadIdx.x == 0) {
            double s = dws[0] + dws[1] + dws[2] + dws[3]
                     + dws[4] + dws[5] + dws[6] + dws[7];
            out[0] = (float)(s * (double)inv_n);
            g_count = 0;   // reset for next (graph-replayed) call
        }
    }
}

extern "C" void kernel_launch(void* const* d_in, const int* in_sizes, int n_in,
                              void* d_out, int out_size) {
    const float4* in4 = (const float4*)d_in[0];
    float* out = (float*)d_out;
    const long long n = in_sizes[0];              // 25,165,824
    const int threads = 256;
    const int elems_per_thread = 16;
    const int blocks = (int)(n / (threads * elems_per_thread));  // 6144

    tv_fused_kernel<<<blocks, threads>>>(in4, out, (float)(1.0 / (double)n));
}

// round 4
// speedup vs baseline: 1.4408x; 1.4408x over previous
#include <cuda_runtime.h>

// Scratch via __device__ globals (no allocations allowed).
__device__ float    g_part[8192];
__device__ unsigned g_count = 0;   // self-resetting ticket -> deterministic per call

// MUFU sqrt: single instruction, max rel err ~2^-23, sqrt(0)=0.
__device__ __forceinline__ float fsqrt_approx(float x) {
    float r;
    asm("sqrt.approx.f32 %0, %1;" : "=f"(r) : "f"(x));
    return r;
}

// Shapes fixed: [8,3,16,256,256] fp32 -> 384 planes of 256x256. Row = 64 float4.
// Each thread: 16-wide segment (4 float4) x 8 consecutive rows, with vertical
// register reuse (row h's loads are reused as the 'a'-row of iteration h+1).
// TV magnitude: sqrt((x[h,w]-x[h,w+1])^2 + (x[h,w]-x[h+1,w])^2), circular.
__global__ void __launch_bounds__(128) tv_fused_kernel(const float4* __restrict__ in4,
                                                       float* __restrict__ out,
                                                       double inv_n) {
    const int t     = blockIdx.x * 128 + threadIdx.x;
    const int plane = t >> 9;                 // 512 threads per 256x256 plane
    const int s     = t & 511;
    const int w4    = (s & 15) << 2;          // float4 offset within row (0..60)
    const int h0    = (s >> 4) << 3;          // first row of this thread's strip
    const int wrapf = (((w4 + 4) & 63) << 2); // scalar float index of right-wrap elem

    const float4* __restrict__ p = in4 + (plane << 14);   // 16384 float4 per plane

    // Load first 'a'-row (h0)
    const float4* rp = p + (h0 << 6);
    float4 a0 = rp[w4], a1 = rp[w4 + 1], a2 = rp[w4 + 2], a3 = rp[w4 + 3];
    float  axn = ((const float*)rp)[wrapf];   // x[h, w+16] (circular)

    float acc = 0.0f;

    #pragma unroll
    for (int i = 1; i <= 8; i++) {
        const int h = (h0 + i) & 255;         // only i==8 can wrap
        const float4* cp = p + (h << 6);
        float4 c0 = cp[w4], c1 = cp[w4 + 1], c2 = cp[w4 + 2], c3 = cp[w4 + 3];
        float  cxn = 0.0f;
        if (i < 8) cxn = ((const float*)cp)[wrapf];  // wrap only needed when c becomes a

        #define TV_PROC(a, nx, c)                                          \
        {                                                                  \
            float dx0 = a.x - a.y,  dy0 = a.x - c.x;                       \
            float dx1 = a.y - a.z,  dy1 = a.y - c.y;                       \
            float dx2 = a.z - a.w,  dy2 = a.z - c.z;                       \
            float dx3 = a.w - (nx), dy3 = a.w - c.w;                       \
            acc += fsqrt_approx(fmaf(dx0, dx0, dy0 * dy0));                \
            acc += fsqrt_approx(fmaf(dx1, dx1, dy1 * dy1));                \
            acc += fsqrt_approx(fmaf(dx2, dx2, dy2 * dy2));                \
            acc += fsqrt_approx(fmaf(dx3, dx3, dy3 * dy3));                \
        }
        TV_PROC(a0, a1.x, c0)
        TV_PROC(a1, a2.x, c1)
        TV_PROC(a2, a3.x, c2)
        TV_PROC(a3, axn,  c3)
        #undef TV_PROC

        a0 = c0; a1 = c1; a2 = c2; a3 = c3; axn = cxn;
    }

    // Warp reduce (4 warps per block)
    #pragma unroll
    for (int o = 16; o > 0; o >>= 1)
        acc += __shfl_xor_sync(0xFFFFFFFFu, acc, o);

    __shared__ float warpsum[4];
    __shared__ bool  s_last;
    const int lane = threadIdx.x & 31;
    const int wid  = threadIdx.x >> 5;
    if (lane == 0) warpsum[wid] = acc;
    if (threadIdx.x == 0) s_last = false;
    __syncthreads();

    if (threadIdx.x == 0) {
        float bsum = warpsum[0] + warpsum[1] + warpsum[2] + warpsum[3];
        g_part[blockIdx.x] = bsum;
        __threadfence();
        unsigned ticket = atomicAdd(&g_count, 1u);
        if (ticket == gridDim.x - 1) s_last = true;
    }
    __syncthreads();

    // Last block to arrive reduces all partials and writes the output.
    if (s_last) {
        double d = 0.0;
        for (int i = threadIdx.x; i < (int)gridDim.x; i += 128)
            d += (double)g_part[i];
        #pragma unroll
        for (int o = 16; o > 0; o >>= 1)
            d += __shfl_xor_sync(0xFFFFFFFFu, d, o);
        __shared__ double dws[4];
        if (lane == 0) dws[wid] = d;
        __syncthreads();
        if (threadIdx.x == 0) {
            double ssum = dws[0] + dws[1] + dws[2] + dws[3];
            out[0] = (float)(ssum * inv_n);
            g_count = 0;   // reset for next (graph-replayed) call
        }
    }
}

extern "C" void kernel_launch(void* const* d_in, const int* in_sizes, int n_in,
                              void* d_out, int out_size) {
    const float4* in4 = (const float4*)d_in[0];
    float* out = (float*)d_out;
    const long long n = in_sizes[0];              // 25,165,824
    // 384 planes * 512 threads/plane = 196608 threads = 1536 blocks * 128
    const int threads = 128;
    const int blocks  = (int)(n / (threads * 128));  // 128 elems per thread -> 1536

    tv_fused_kernel<<<blocks, threads>>>(in4, out, 1.0 / (double)n);
}

// round 5
// speedup vs baseline: 1.4615x; 1.0144x over previous
#include <cuda_runtime.h>

// Scratch via __device__ globals (no allocations allowed).
__device__ float    g_part[8192];
__device__ unsigned g_count = 0;   // self-resetting ticket -> deterministic per call

// MUFU sqrt: single instruction, max rel err ~2^-23, sqrt(0)=0.
__device__ __forceinline__ float fsqrt_approx(float x) {
    float r;
    asm("sqrt.approx.f32 %0, %1;" : "=f"(r) : "f"(x));
    return r;
}

// Shapes fixed: [8,3,16,256,256] fp32 -> 384 planes of 256x256. Row = 64 float4.
// Each thread: 16-wide segment (4 float4) x 4 consecutive rows, vertical register
// reuse (row h's loads are next iteration's 'a'-row). Lanes 0-15 of a warp tile a
// full 256-wide row, so the circular right-wrap value x[h, w+16] is the next
// lane's c0.x -> fetched with __shfl_sync instead of a scalar load.
// TV magnitude: sqrt((x[h,w]-x[h,w+1])^2 + (x[h,w]-x[h+1,w])^2), circular.
__global__ void __launch_bounds__(128) tv_fused_kernel(const float4* __restrict__ in4,
                                                       float* __restrict__ out,
                                                       double inv_n) {
    const int t     = blockIdx.x * 128 + threadIdx.x;
    const int plane = t >> 10;                // 1024 threads per 256x256 plane
    const int s     = t & 1023;
    const int w4    = (s & 15) << 2;          // float4 offset within row (0..60)
    const int h0    = (s >> 4) << 2;          // first row of this thread's 4-row strip

    const int lane   = threadIdx.x & 31;
    const int nbr    = (lane & 16) | ((lane + 1) & 15);   // right neighbor in 16-lane row group
    const unsigned FULL = 0xFFFFFFFFu;

    const float4* __restrict__ p = in4 + (plane << 14);   // 16384 float4 per plane

    // Load first 'a'-row (h0)
    const float4* rp = p + (h0 << 6);
    float4 a0 = rp[w4], a1 = rp[w4 + 1], a2 = rp[w4 + 2], a3 = rp[w4 + 3];
    float  axn = __shfl_sync(FULL, a0.x, nbr);   // x[h, w+16] (circular)

    float acc = 0.0f;

    #pragma unroll
    for (int i = 1; i <= 4; i++) {
        const int h = (h0 + i) & 255;         // wraps only for the last strip
        const float4* cp = p + (h << 6);
        float4 c0 = cp[w4], c1 = cp[w4 + 1], c2 = cp[w4 + 2], c3 = cp[w4 + 3];
        float  cxn = __shfl_sync(FULL, c0.x, nbr);

        #define TV_PROC(a, nx, c)                                          \
        {                                                                  \
            float dx0 = a.x - a.y,  dy0 = a.x - c.x;                       \
            float dx1 = a.y - a.z,  dy1 = a.y - c.y;                       \
            float dx2 = a.z - a.w,  dy2 = a.z - c.z;                       \
            float dx3 = a.w - (nx), dy3 = a.w - c.w;                       \
            acc += fsqrt_approx(fmaf(dx0, dx0, dy0 * dy0));                \
            acc += fsqrt_approx(fmaf(dx1, dx1, dy1 * dy1));                \
            acc += fsqrt_approx(fmaf(dx2, dx2, dy2 * dy2));                \
            acc += fsqrt_approx(fmaf(dx3, dx3, dy3 * dy3));                \
        }
        TV_PROC(a0, a1.x, c0)
        TV_PROC(a1, a2.x, c1)
        TV_PROC(a2, a3.x, c2)
        TV_PROC(a3, axn,  c3)
        #undef TV_PROC

        a0 = c0; a1 = c1; a2 = c2; a3 = c3; axn = cxn;
    }

    // Warp reduce (4 warps per block)
    #pragma unroll
    for (int o = 16; o > 0; o >>= 1)
        acc += __shfl_xor_sync(FULL, acc, o);

    __shared__ float warpsum[4];
    __shared__ bool  s_last;
    const int wid = threadIdx.x >> 5;
    if (lane == 0) warpsum[wid] = acc;
    if (threadIdx.x == 0) s_last = false;
    __syncthreads();

    if (threadIdx.x == 0) {
        float bsum = warpsum[0] + warpsum[1] + warpsum[2] + warpsum[3];
        g_part[blockIdx.x] = bsum;
        __threadfence();
        unsigned ticket = atomicAdd(&g_count, 1u);
        if (ticket == gridDim.x - 1) s_last = true;
    }
    __syncthreads();

    // Last block to arrive reduces all partials and writes the output.
    if (s_last) {
        double d = 0.0;
        for (int i = threadIdx.x; i < (int)gridDim.x; i += 128)
            d += (double)g_part[i];
        #pragma unroll
        for (int o = 16; o > 0; o >>= 1)
            d += __shfl_xor_sync(FULL, d, o);
        __shared__ double dws[4];
        if (lane == 0) dws[wid] = d;
        __syncthreads();
        if (threadIdx.x == 0) {
            double ssum = dws[0] + dws[1] + dws[2] + dws[3];
            out[0] = (float)(ssum * inv_n);
            g_count = 0;   // reset for next (graph-replayed) call
        }
    }
}

extern "C" void kernel_launch(void* const* d_in, const int* in_sizes, int n_in,
                              void* d_out, int out_size) {
    const float4* in4 = (const float4*)d_in[0];
    float* out = (float*)d_out;
    const long long n = in_sizes[0];              // 25,165,824
    // 384 planes * 1024 threads/plane = 393216 threads = 3072 blocks * 128
    const int threads = 128;
    const int blocks  = (int)(n / (threads * 64));  // 64 elems per thread -> 3072

    tv_fused_kernel<<<blocks, threads>>>(in4, out, 1.0 / (double)n);
}